// round 13
// baseline (speedup 1.0000x reference)
#include <cuda_runtime.h>
#include <cuda_bf16.h>
#include <cstdint>
#include <math.h>

#define SEQ_LEN 20
#define NF      812
#define HID     400
#define VARIDX  811
#define BATCH   8192
#define NPCOL   1664        // 13 blocks of 128 packed cols
#define VW      832         // values row width: feats(VARIDX=0) + mask@812 + pad
#define HW      448         // h row width (7 chunks of 64)
#define KP2     1280        // fused K = 448 + 832 = 20 chunks of 64
#define NCH     20
#define AB2     (128*144)   // 18432: 128 rows x 144B (64 bf16 data + 8 pad)
#define STG     (2*AB2)     // 36864
#define NSTG    3
#define SMEMSZ  (NSTG*STG)  // 110592

// ---------------- device scratch ----------------
__device__ float g_c[BATCH*HID];
__device__ __nv_bfloat16 g_hbf[2][BATCH*HW];       // decayed h bf16, ping-pong
__device__ __nv_bfloat16 g_vbf[(size_t)SEQ_LEN*BATCH*VW];
__device__ __nv_bfloat16 g_Wbf[(size_t)NPCOL*KP2];
__device__ float g_W811[NPCOL];
__device__ float g_biasP[NPCOL];
__device__ float g_xhp[26][BATCH];                 // xh dot partials (13 colBlk x 2 wn)
__device__ float g_xvar[BATCH];
__device__ float g_wsum[HID];
__device__ float g_numbuf[SEQ_LEN][BATCH];
__device__ float g_denbuf[SEQ_LEN][BATCH];
__device__ float g_stepw[SEQ_LEN];

// ---------------- helpers ----------------
__device__ __forceinline__ uint32_t smem_u32(const void* p) {
    uint32_t a;
    asm("{ .reg .u64 t; cvta.to.shared.u64 t, %1; cvt.u32.u64 %0, t; }" : "=r"(a) : "l"(p));
    return a;
}
__device__ __forceinline__ void cp16(uint32_t dst, const void* src) {
    asm volatile("cp.async.cg.shared.global [%0], [%1], 16;" :: "r"(dst), "l"(src));
}
__device__ __forceinline__ void ldsm4(uint32_t& r0, uint32_t& r1, uint32_t& r2, uint32_t& r3,
                                      uint32_t addr) {
    asm volatile("ldmatrix.sync.aligned.m8n8.x4.shared.b16 {%0,%1,%2,%3}, [%4];"
        : "=r"(r0), "=r"(r1), "=r"(r2), "=r"(r3) : "r"(addr));
}
__device__ __forceinline__ void mma_bf16(float* c, uint32_t a0, uint32_t a1, uint32_t a2, uint32_t a3,
                                         uint32_t b0, uint32_t b1) {
    asm volatile("mma.sync.aligned.m16n8k16.row.col.f32.bf16.bf16.f32 "
        "{%0,%1,%2,%3}, {%4,%5,%6,%7}, {%8,%9}, {%0,%1,%2,%3};"
        : "+f"(c[0]), "+f"(c[1]), "+f"(c[2]), "+f"(c[3])
        : "r"(a0), "r"(a1), "r"(a2), "r"(a3), "r"(b0), "r"(b1));
}

// ---------------- init ----------------
__global__ void k_init(const float* __restrict__ W_decay) {
    int idx = blockIdx.x*blockDim.x + threadIdx.x;
    if (idx < BATCH*HW) {
        g_hbf[0][idx] = __float2bfloat16(0.f);
        g_hbf[1][idx] = __float2bfloat16(0.f);
    }
    if (idx < BATCH*HID) g_c[idx] = 0.f;
    if (idx < 26*BATCH) (&g_xhp[0][0])[idx] = 0.f;
    if (idx < HID) {
        const float* row = W_decay + (size_t)idx*NF;
        float s = 0.f;
        for (int f = 0; f < NF; f++) s += row[f];
        g_wsum[idx] = s;
    }
}

// ---------------- prepack values (+mask@812), VARIDX zeroed, time-major ----------------
__global__ void k_vpack(const float* __restrict__ values, const float* __restrict__ masks) {
    size_t idx = (size_t)blockIdx.x*blockDim.x + threadIdx.x;
    if (idx >= (size_t)SEQ_LEN*BATCH*VW) return;
    int v = idx % VW;
    size_t r = idx / VW;
    int b = r % BATCH, t = r / BATCH;
    float x = 0.f;
    if (v < NF && v != VARIDX) x = values[((size_t)b*SEQ_LEN + t)*NF + v];
    else if (v == NF)          x = masks[b*SEQ_LEN + t];
    g_vbf[idx] = __float2bfloat16(x);
}

// ---------------- pack fused weights [W_hh pad448 | W_ih feats+mask pad832] ----------------
__global__ void k_pack(const float* __restrict__ W_ih, const float* __restrict__ W_hh,
                       const float* __restrict__ b_ih, const float* __restrict__ b_hh) {
    size_t idx = (size_t)blockIdx.x*blockDim.x + threadIdx.x;
    if (idx >= (size_t)NPCOL*KP2) return;
    int p = idx / KP2, k = idx % KP2;
    int colBlk = p >> 7, pb = p & 127;
    int wn = pb >> 6, rr = pb & 63, nf = rr >> 3, c = rr & 7;
    int gate = nf >> 1, sb = nf & 1;
    int unit = colBlk*32 + wn*16 + sb*8 + c;
    bool valid = (unit < HID);
    int orig = gate*HID + unit;
    float v = 0.f;
    if (valid) {
        if (k < HW) {
            if (k < HID) v = W_hh[(size_t)orig*HID + k];
        } else {
            int kk = k - HW;
            if (kk < NF && kk != VARIDX) v = W_ih[(size_t)orig*(NF+1) + kk];
            else if (kk == NF)           v = W_ih[(size_t)orig*(NF+1) + NF];
        }
    }
    g_Wbf[idx] = __float2bfloat16(v);
    if (k == 0) {
        g_W811[p]  = valid ? W_ih[(size_t)orig*(NF+1) + VARIDX] : 0.f;
        g_biasP[p] = valid ? (b_ih[orig] + b_hh[orig])          : 0.f;
    }
}

// ---------------- per-step xh finalize (reads 26 partials) ----------------
__global__ void __launch_bounds__(256) k_xh(
    const float* __restrict__ values, const float* __restrict__ masks,
    const float* __restrict__ b_reg, float* __restrict__ out_imp, int t)
{
    int b = blockIdx.x*256 + threadIdx.x;
    float s = b_reg[0];
    #pragma unroll
    for (int j = 0; j < 26; j++) s += g_xhp[j][b];
    float m = masks[b*SEQ_LEN + t];
    float xo = values[((size_t)b*SEQ_LEN + t)*NF + VARIDX];
    float xv = xo*m + (1.f - m)*s;
    g_xvar[b] = xv;
    out_imp[b*SEQ_LEN + t] = xv;
    g_numbuf[t][b] = m * fabsf(xo - s);
    g_denbuf[t][b] = m;
}

// ---------------- fused per-step GEMM (128x128, k64 chunks, 3-stage) ----------------
__global__ void __launch_bounds__(256, 2) k_step(
    const float* __restrict__ deltas, const float* __restrict__ b_decay,
    const float* __restrict__ W_reg, int t)
{
    extern __shared__ char smem[];
    uint32_t sb = smem_u32(smem);
    int tid = threadIdx.x;
    int warp = tid >> 5, lane = tid & 31, q = lane & 3, rq = lane >> 2;
    int wm = warp & 3, wn = warp >> 2;
    int rowBase = blockIdx.y * 128;
    int colBlk = blockIdx.x;
    __nv_bfloat16* hbf_out = g_hbf[(t+1) & 1];

    // ---- hoisted load pointers: thread -> (row/col = tid>>1, half = tid&1) ----
    int r2 = tid >> 1, hf = tid & 1;
    const __nv_bfloat16* aH = g_hbf[t & 1] + (size_t)(rowBase + r2)*HW + hf*32;
    const __nv_bfloat16* aV = g_vbf + ((size_t)t*BATCH + rowBase + r2)*VW + hf*32;
    const __nv_bfloat16* bW = g_Wbf + (size_t)(colBlk*128 + r2)*KP2 + hf*32;
    uint32_t aDst = (uint32_t)(r2*144 + hf*64);
    uint32_t bDst = (uint32_t)(AB2 + r2*144 + hf*64);

    // ---- ldsm addresses (144B row stride: conflict-free) ----
    int l8 = lane & 7, lb = (lane >> 3) & 1, lh = lane >> 4;
    uint32_t aAddr = sb + (uint32_t)((wm*32 + l8 + lb*8)*144 + lh*16);
    uint32_t bAddr = sb + (uint32_t)(AB2 + (wn*64 + l8 + lb*8)*144 + lh*16);

    float acc[2][8][4];
    #pragma unroll
    for (int mi = 0; mi < 2; mi++)
        #pragma unroll
        for (int nf = 0; nf < 8; nf++)
            #pragma unroll
            for (int j = 0; j < 4; j++) acc[mi][nf][j] = 0.f;

#define ISSUE(KT, S) do {                                                      \
        uint32_t _b = sb + (uint32_t)((S)*STG);                                \
        const __nv_bfloat16* _a = ((KT) < 7) ? aH + (KT)*64 : aV + ((KT)-7)*64;\
        _Pragma("unroll")                                                      \
        for (int i = 0; i < 4; i++) cp16(_b + aDst + i*16, _a + i*8);          \
        const __nv_bfloat16* _w = bW + (KT)*64;                                \
        _Pragma("unroll")                                                      \
        for (int i = 0; i < 4; i++) cp16(_b + bDst + i*16, _w + i*8);          \
        asm volatile("cp.async.commit_group;" ::: "memory");                   \
    } while (0)

    ISSUE(0, 0); ISSUE(1, 1);

    int cs = 0;
    #pragma unroll 1
    for (int kt = 0; kt < NCH; kt++) {
        if (kt < NCH-1) asm volatile("cp.async.wait_group 1;" ::: "memory");
        else            asm volatile("cp.async.wait_group 0;" ::: "memory");
        __syncthreads();
        if (kt + 2 < NCH) {
            int is = cs + 2; if (is >= NSTG) is -= NSTG;
            ISSUE(kt+2, is);
        }
        uint32_t ab = aAddr + (uint32_t)(cs*STG);
        uint32_t bb = bAddr + (uint32_t)(cs*STG);
        if (++cs == NSTG) cs = 0;
        #pragma unroll
        for (int s = 0; s < 4; s++) {
            uint32_t a[2][4];
            #pragma unroll
            for (int mi = 0; mi < 2; mi++)
                ldsm4(a[mi][0], a[mi][1], a[mi][2], a[mi][3], ab + mi*2304 + s*32);
            #pragma unroll
            for (int nfp = 0; nfp < 4; nfp++) {
                uint32_t b0, b1, b2, b3;
                ldsm4(b0, b1, b2, b3, bb + nfp*2304 + s*32);
                #pragma unroll
                for (int mi = 0; mi < 2; mi++) {
                    mma_bf16(acc[mi][nfp*2+0], a[mi][0], a[mi][1], a[mi][2], a[mi][3], b0, b2);
                    mma_bf16(acc[mi][nfp*2+1], a[mi][0], a[mi][1], a[mi][2], a[mi][3], b1, b3);
                }
            }
        }
    }
#undef ISSUE

    // ---- epilogue: gates -> LSTM -> c, decayed h(t+1), xh partials ----
    int colW = colBlk*128 + wn*64;
    int row_b = rowBase + wm*32 + rq;
    bool wr_h = (t+1 < SEQ_LEN);
    float part[4] = {0.f, 0.f, 0.f, 0.f};
    #pragma unroll
    for (int sbx = 0; sbx < 2; sbx++) {
        int u0 = colBlk*32 + wn*16 + sbx*8 + 2*q;
        if (u0 >= HID) continue;
        float2 ws = *(const float2*)&g_wsum[u0];
        float2 bd = *(const float2*)&b_decay[u0];
        float2 wr = *(const float2*)&W_reg[u0];
        float2 bi2 = *(const float2*)&g_biasP[colW + (0+sbx)*8 + 2*q];
        float2 bf2 = *(const float2*)&g_biasP[colW + (2+sbx)*8 + 2*q];
        float2 bg2 = *(const float2*)&g_biasP[colW + (4+sbx)*8 + 2*q];
        float2 bo2 = *(const float2*)&g_biasP[colW + (6+sbx)*8 + 2*q];
        float2 w8i = *(const float2*)&g_W811[colW + (0+sbx)*8 + 2*q];
        float2 w8f = *(const float2*)&g_W811[colW + (2+sbx)*8 + 2*q];
        float2 w8g = *(const float2*)&g_W811[colW + (4+sbx)*8 + 2*q];
        float2 w8o = *(const float2*)&g_W811[colW + (6+sbx)*8 + 2*q];
        #pragma unroll
        for (int mi = 0; mi < 2; mi++) {
            #pragma unroll
            for (int r = 0; r < 2; r++) {
                int row = row_b + mi*16 + r*8;
                float xv = g_xvar[row];
                int e = r*2;
                float ig0 = acc[mi][0+sbx][e]   + bi2.x + xv*w8i.x;
                float ig1 = acc[mi][0+sbx][e+1] + bi2.y + xv*w8i.y;
                float fg0 = acc[mi][2+sbx][e]   + bf2.x + xv*w8f.x;
                float fg1 = acc[mi][2+sbx][e+1] + bf2.y + xv*w8f.y;
                float gg0 = acc[mi][4+sbx][e]   + bg2.x + xv*w8g.x;
                float gg1 = acc[mi][4+sbx][e+1] + bg2.y + xv*w8g.y;
                float og0 = acc[mi][6+sbx][e]   + bo2.x + xv*w8o.x;
                float og1 = acc[mi][6+sbx][e+1] + bo2.y + xv*w8o.y;
                float2 cin = *(float2*)&g_c[(size_t)row*HID + u0];
                float si0 = 1.f/(1.f + expf(-ig0)), si1 = 1.f/(1.f + expf(-ig1));
                float sf0 = 1.f/(1.f + expf(-fg0)), sf1 = 1.f/(1.f + expf(-fg1));
                float so0 = 1.f/(1.f + expf(-og0)), so1 = 1.f/(1.f + expf(-og1));
                float c0 = sf0*cin.x + si0*tanhf(gg0);
                float c1 = sf1*cin.y + si1*tanhf(gg1);
                *(float2*)&g_c[(size_t)row*HID + u0] = make_float2(c0, c1);
                if (wr_h) {
                    float h0 = so0*tanhf(c0);
                    float h1 = so1*tanhf(c1);
                    float d = deltas[row*SEQ_LEN + t + 1];
                    float hd0 = h0 * expf(-fmaxf(d*ws.x + bd.x, 0.f));
                    float hd1 = h1 * expf(-fmaxf(d*ws.y + bd.y, 0.f));
                    __nv_bfloat162 hp;
                    hp.x = __float2bfloat16(hd0);
                    hp.y = __float2bfloat16(hd1);
                    *(__nv_bfloat162*)&hbf_out[(size_t)row*HW + u0] = hp;
                    part[mi*2+r] += hd0*wr.x + hd1*wr.y;
                }
            }
        }
    }
    // quad-reduce xh partials over q lanes, write one float per (group,row)
    if (wr_h) {
        #pragma unroll
        for (int e = 0; e < 4; e++) {
            part[e] += __shfl_xor_sync(0xffffffffu, part[e], 1);
            part[e] += __shfl_xor_sync(0xffffffffu, part[e], 2);
        }
        if (q == 0) {
            int grp = colBlk*2 + wn;
            #pragma unroll
            for (int mi = 0; mi < 2; mi++)
                #pragma unroll
                for (int r = 0; r < 2; r++)
                    g_xhp[grp][row_b + mi*16 + r*8] = part[mi*2+r];
        }
    }
}

// ---------------- deterministic loss reduction ----------------
__global__ void k_loss1() {
    int t = blockIdx.x, tid = threadIdx.x;
    float sn = 0.f, sd = 0.f;
    for (int b = tid; b < BATCH; b += 256) { sn += g_numbuf[t][b]; sd += g_denbuf[t][b]; }
    __shared__ float rn[256], rd[256];
    rn[tid] = sn; rd[tid] = sd;
    __syncthreads();
    for (int o = 128; o > 0; o >>= 1) {
        if (tid < o) { rn[tid] += rn[tid+o]; rd[tid] += rd[tid+o]; }
        __syncthreads();
    }
    if (tid == 0) g_stepw[t] = rn[0] / (rd[0] + 1e-5f);
}
__global__ void k_loss2(float* __restrict__ out) {
    if (threadIdx.x == 0 && blockIdx.x == 0) {
        float s = 0.f;
        for (int t = 0; t < SEQ_LEN; t++) s += g_stepw[t];
        out[0] = s / (float)SEQ_LEN;
    }
}

extern "C" void kernel_launch(void* const* d_in, const int* in_sizes, int n_in,
                              void* d_out, int out_size) {
    const float* values  = (const float*)d_in[0];
    const float* masks   = (const float*)d_in[1];
    const float* deltas  = (const float*)d_in[2];
    const float* W_decay = (const float*)d_in[3];
    const float* b_decay = (const float*)d_in[4];
    const float* W_reg   = (const float*)d_in[5];
    const float* b_reg   = (const float*)d_in[6];
    const float* W_ih    = (const float*)d_in[7];
    const float* W_hh    = (const float*)d_in[8];
    const float* b_ih    = (const float*)d_in[9];
    const float* b_hh    = (const float*)d_in[10];
    float* out = (float*)d_out;
    float* out_imp = out + 1;

    cudaFuncSetAttribute(k_step, cudaFuncAttributeMaxDynamicSharedMemorySize, SMEMSZ);

    k_init<<<(BATCH*HW + 255)/256, 256>>>(W_decay);
    k_vpack<<<(int)(((size_t)SEQ_LEN*BATCH*VW + 255)/256), 256>>>(values, masks);
    k_pack<<<(int)(((size_t)NPCOL*KP2 + 255)/256), 256>>>(W_ih, W_hh, b_ih, b_hh);

    for (int t = 0; t < SEQ_LEN; t++) {
        k_xh<<<BATCH/256, 256>>>(values, masks, b_reg, out_imp, t);
        dim3 grid(13, BATCH/128);          // (13, 64)
        k_step<<<grid, 256, SMEMSZ>>>(deltas, b_decay, W_reg, t);
    }
    k_loss1<<<SEQ_LEN, 256>>>();
    k_loss2<<<1, 32>>>(out);
}

// round 16
// speedup vs baseline: 1.2093x; 1.2093x over previous
#include <cuda_runtime.h>
#include <cuda_bf16.h>
#include <cstdint>
#include <math.h>

#define SEQ_LEN 20
#define NF      812
#define HID     400
#define VARIDX  811
#define BATCH   8192
#define NPCOL   1664        // 13 blocks of 128 packed cols
#define VW      832         // values row width: feats(VARIDX=0) + mask@812 + pad
#define HW      416         // h row width (13 chunks of 32)
#define KP2     1248        // fused K = 416 + 832 = 39 chunks of 32
#define NCH     39
#define ABYTES  (128*80)    // 10240
#define BUFB    (2*ABYTES)  // 20480
#define NSTG    4
#define SMEMSZ  (NSTG*BUFB) // 81920

// ---------------- device scratch ----------------
__device__ float g_c[BATCH*HID];
__device__ __nv_bfloat16 g_hbf[2][BATCH*HW];       // decayed h bf16, ping-pong
__device__ __nv_bfloat16 g_vbf[(size_t)SEQ_LEN*BATCH*VW];
__device__ __nv_bfloat16 g_Wbf[(size_t)NPCOL*KP2];
__device__ float g_W811[NPCOL];
__device__ float g_biasP[NPCOL];
__device__ float g_xhp[26][BATCH];                 // xh dot partials
__device__ float g_xvar[BATCH];
__device__ float g_wsum[HID];
__device__ float g_numbuf[SEQ_LEN][BATCH];
__device__ float g_denbuf[SEQ_LEN][BATCH];
__device__ float g_stepw[SEQ_LEN];

// ---------------- helpers ----------------
__device__ __forceinline__ uint32_t smem_u32(const void* p) {
    uint32_t a;
    asm("{ .reg .u64 t; cvta.to.shared.u64 t, %1; cvt.u32.u64 %0, t; }" : "=r"(a) : "l"(p));
    return a;
}
__device__ __forceinline__ void cp16(uint32_t dst, const void* src) {
    asm volatile("cp.async.cg.shared.global [%0], [%1], 16;" :: "r"(dst), "l"(src));
}
__device__ __forceinline__ void ldsm4(uint32_t& r0, uint32_t& r1, uint32_t& r2, uint32_t& r3,
                                      uint32_t addr) {
    asm volatile("ldmatrix.sync.aligned.m8n8.x4.shared.b16 {%0,%1,%2,%3}, [%4];"
        : "=r"(r0), "=r"(r1), "=r"(r2), "=r"(r3) : "r"(addr));
}
__device__ __forceinline__ void mma_bf16(float* c, uint32_t a0, uint32_t a1, uint32_t a2, uint32_t a3,
                                         uint32_t b0, uint32_t b1) {
    asm volatile("mma.sync.aligned.m16n8k16.row.col.f32.bf16.bf16.f32 "
        "{%0,%1,%2,%3}, {%4,%5,%6,%7}, {%8,%9}, {%0,%1,%2,%3};"
        : "+f"(c[0]), "+f"(c[1]), "+f"(c[2]), "+f"(c[3])
        : "r"(a0), "r"(a1), "r"(a2), "r"(a3), "r"(b0), "r"(b1));
}

// ---------------- init (re-run every launch: graph-replay determinism) ----------------
__global__ void k_init(const float* __restrict__ W_decay) {
    int idx = blockIdx.x*blockDim.x + threadIdx.x;
    if (idx < BATCH*HW) {
        g_hbf[0][idx] = __float2bfloat16(0.f);
        g_hbf[1][idx] = __float2bfloat16(0.f);
    }
    if (idx < BATCH*HID) g_c[idx] = 0.f;
    if (idx < 26*BATCH) (&g_xhp[0][0])[idx] = 0.f;
    if (idx < HID) {
        const float* row = W_decay + (size_t)idx*NF;
        float s = 0.f;
        for (int f = 0; f < NF; f++) s += row[f];
        g_wsum[idx] = s;
    }
}

// ---------------- prepack values (+mask@812), VARIDX zeroed, time-major ----------------
__global__ void k_vpack(const float* __restrict__ values, const float* __restrict__ masks) {
    size_t idx = (size_t)blockIdx.x*blockDim.x + threadIdx.x;
    if (idx >= (size_t)SEQ_LEN*BATCH*VW) return;
    int v = idx % VW;
    size_t r = idx / VW;
    int b = r % BATCH, t = r / BATCH;
    float x = 0.f;
    if (v < NF && v != VARIDX) x = values[((size_t)b*SEQ_LEN + t)*NF + v];
    else if (v == NF)          x = masks[b*SEQ_LEN + t];
    g_vbf[idx] = __float2bfloat16(x);
}

// ---------------- pack fused weights [W_hh pad416 | W_ih feats(VARIDX=0)+mask pad832] ----------------
__global__ void k_pack(const float* __restrict__ W_ih, const float* __restrict__ W_hh,
                       const float* __restrict__ b_ih, const float* __restrict__ b_hh) {
    size_t idx = (size_t)blockIdx.x*blockDim.x + threadIdx.x;
    if (idx >= (size_t)NPCOL*KP2) return;
    int p = idx / KP2, k = idx % KP2;
    int colBlk = p >> 7, pb = p & 127;
    int wn = pb >> 6, rr = pb & 63, nf = rr >> 3, c = rr & 7;
    int gate = nf >> 1, sb = nf & 1;
    int unit = colBlk*32 + wn*16 + sb*8 + c;
    bool valid = (unit < HID);
    int orig = gate*HID + unit;
    float v = 0.f;
    if (valid) {
        if (k < HW) {
            if (k < HID) v = W_hh[(size_t)orig*HID + k];
        } else {
            int kk = k - HW;
            if (kk < NF && kk != VARIDX) v = W_ih[(size_t)orig*(NF+1) + kk];
            else if (kk == NF)           v = W_ih[(size_t)orig*(NF+1) + NF];
        }
    }
    g_Wbf[idx] = __float2bfloat16(v);
    if (k == 0) {
        g_W811[p]  = valid ? W_ih[(size_t)orig*(NF+1) + VARIDX] : 0.f;
        g_biasP[p] = valid ? (b_ih[orig] + b_hh[orig])          : 0.f;
    }
}

// ---------------- per-step xh finalize ----------------
__global__ void __launch_bounds__(256) k_xh(
    const float* __restrict__ values, const float* __restrict__ masks,
    const float* __restrict__ b_reg, float* __restrict__ out_imp, int t)
{
    int b = blockIdx.x*256 + threadIdx.x;
    float s = b_reg[0];
    #pragma unroll
    for (int j = 0; j < 26; j++) s += g_xhp[j][b];
    float m = masks[b*SEQ_LEN + t];
    float xo = values[((size_t)b*SEQ_LEN + t)*NF + VARIDX];
    float xv = xo*m + (1.f - m)*s;
    g_xvar[b] = xv;
    out_imp[b*SEQ_LEN + t] = xv;
    g_numbuf[t][b] = m * fabsf(xo - s);
    g_denbuf[t][b] = m;
}

// ---------------- fused per-step GEMM (R6 engine) + LSTM + decay + xh partials ----------------
__global__ void __launch_bounds__(256, 2) k_step(
    const float* __restrict__ deltas, const float* __restrict__ b_decay,
    const float* __restrict__ W_reg, int t)
{
    extern __shared__ char smem[];
    uint32_t sb = smem_u32(smem);
    int tid = threadIdx.x;
    int warp = tid >> 5, lane = tid & 31, q = lane & 3, rq = lane >> 2;
    int wm = warp & 3, wn = warp >> 2;
    int rowBase = blockIdx.y * 128;
    int colBlk = blockIdx.x;
    __nv_bfloat16* hbf_out = g_hbf[(t+1) & 1];

    // hoisted load pointers: 4 threads/row, rows r4 and r4+64
    int r4 = tid >> 2, c4 = tid & 3;
    const __nv_bfloat16* aH0 = g_hbf[t & 1] + (size_t)(rowBase + r4)*HW + c4*8;
    const __nv_bfloat16* aH1 = aH0 + (size_t)64*HW;
    const __nv_bfloat16* aV0 = g_vbf + ((size_t)t*BATCH + rowBase + r4)*VW + c4*8;
    const __nv_bfloat16* aV1 = aV0 + (size_t)64*VW;
    const __nv_bfloat16* bW0 = g_Wbf + (size_t)(colBlk*128 + r4)*KP2 + c4*8;
    const __nv_bfloat16* bW1 = bW0 + (size_t)64*KP2;
    uint32_t aD0 = (uint32_t)(r4*80 + c4*16),        aD1 = aD0 + 64*80;
    uint32_t bD0 = (uint32_t)(ABYTES + r4*80 + c4*16), bD1 = bD0 + 64*80;

    // ldsm addresses (80B row stride, conflict-free)
    int l8 = lane & 7, lb = (lane >> 3) & 1, lh = lane >> 4;
    uint32_t aAddr = sb + (uint32_t)((wm*32 + l8 + lb*8)*80 + lh*16);
    uint32_t bAddr = sb + (uint32_t)(ABYTES + (wn*64 + l8 + lb*8)*80 + lh*16);

    float acc[2][8][4];
    #pragma unroll
    for (int mi = 0; mi < 2; mi++)
        #pragma unroll
        for (int nf = 0; nf < 8; nf++)
            #pragma unroll
            for (int j = 0; j < 4; j++) acc[mi][nf][j] = 0.f;

#define ISSUE(KT, S) do {                                                          \
        uint32_t _b = sb + (uint32_t)((S)*BUFB);                                   \
        const __nv_bfloat16* _a0 = ((KT) < 13) ? aH0 + (KT)*32 : aV0 + ((KT)-13)*32; \
        const __nv_bfloat16* _a1 = ((KT) < 13) ? aH1 + (KT)*32 : aV1 + ((KT)-13)*32; \
        cp16(_b + aD0, _a0); cp16(_b + aD1, _a1);                                  \
        cp16(_b + bD0, bW0 + (KT)*32); cp16(_b + bD1, bW1 + (KT)*32);              \
        asm volatile("cp.async.commit_group;" ::: "memory");                       \
    } while (0)

    ISSUE(0, 0); ISSUE(1, 1); ISSUE(2, 2);

    #pragma unroll 1
    for (int kt = 0; kt < NCH; kt++) {
        int buf = kt & 3;
        if (kt < NCH-2)       asm volatile("cp.async.wait_group 2;" ::: "memory");
        else if (kt == NCH-2) asm volatile("cp.async.wait_group 1;" ::: "memory");
        else                  asm volatile("cp.async.wait_group 0;" ::: "memory");
        __syncthreads();
        if (kt + 3 < NCH) ISSUE(kt+3, (kt+3) & 3);
        uint32_t ab = aAddr + (uint32_t)(buf*BUFB);
        uint32_t bb = bAddr + (uint32_t)(buf*BUFB);
        #pragma unroll
        for (int s = 0; s < 2; s++) {
            uint32_t a[2][4];
            #pragma unroll
            for (int mi = 0; mi < 2; mi++)
                ldsm4(a[mi][0], a[mi][1], a[mi][2], a[mi][3], ab + mi*1280 + s*32);
            #pragma unroll
            for (int nfp = 0; nfp < 4; nfp++) {
                uint32_t b0, b1, b2, b3;
                ldsm4(b0, b1, b2, b3, bb + nfp*1280 + s*32);
                #pragma unroll
                for (int mi = 0; mi < 2; mi++) {
                    mma_bf16(acc[mi][nfp*2+0], a[mi][0], a[mi][1], a[mi][2], a[mi][3], b0, b2);
                    mma_bf16(acc[mi][nfp*2+1], a[mi][0], a[mi][1], a[mi][2], a[mi][3], b1, b3);
                }
            }
        }
    }
#undef ISSUE

    // ---- epilogue: gates + bias + xv*W811 -> LSTM -> c, decayed h(t+1), xh partials ----
    int colW = colBlk*128 + wn*64;
    int row_b = rowBase + wm*32 + rq;
    bool wr_h = (t+1 < SEQ_LEN);
    float part[4] = {0.f, 0.f, 0.f, 0.f};
    #pragma unroll
    for (int sbx = 0; sbx < 2; sbx++) {
        int u0 = colBlk*32 + wn*16 + sbx*8 + 2*q;
        if (u0 >= HID) continue;
        float2 ws = *(const float2*)&g_wsum[u0];
        float2 bd = *(const float2*)&b_decay[u0];
        float2 wr = *(const float2*)&W_reg[u0];
        float2 bi2 = *(const float2*)&g_biasP[colW + (0+sbx)*8 + 2*q];
        float2 bf2 = *(const float2*)&g_biasP[colW + (2+sbx)*8 + 2*q];
        float2 bg2 = *(const float2*)&g_biasP[colW + (4+sbx)*8 + 2*q];
        float2 bo2 = *(const float2*)&g_biasP[colW + (6+sbx)*8 + 2*q];
        float2 w8i = *(const float2*)&g_W811[colW + (0+sbx)*8 + 2*q];
        float2 w8f = *(const float2*)&g_W811[colW + (2+sbx)*8 + 2*q];
        float2 w8g = *(const float2*)&g_W811[colW + (4+sbx)*8 + 2*q];
        float2 w8o = *(const float2*)&g_W811[colW + (6+sbx)*8 + 2*q];
        #pragma unroll
        for (int mi = 0; mi < 2; mi++) {
            #pragma unroll
            for (int r = 0; r < 2; r++) {
                int row = row_b + mi*16 + r*8;
                float xv = g_xvar[row];
                int e = r*2;
                float ig0 = acc[mi][0+sbx][e]   + bi2.x + xv*w8i.x;
                float ig1 = acc[mi][0+sbx][e+1] + bi2.y + xv*w8i.y;
                float fg0 = acc[mi][2+sbx][e]   + bf2.x + xv*w8f.x;
                float fg1 = acc[mi][2+sbx][e+1] + bf2.y + xv*w8f.y;
                float gg0 = acc[mi][4+sbx][e]   + bg2.x + xv*w8g.x;
                float gg1 = acc[mi][4+sbx][e+1] + bg2.y + xv*w8g.y;
                float og0 = acc[mi][6+sbx][e]   + bo2.x + xv*w8o.x;
                float og1 = acc[mi][6+sbx][e+1] + bo2.y + xv*w8o.y;
                float2 cin = *(float2*)&g_c[(size_t)row*HID + u0];
                float si0 = 1.f/(1.f + expf(-ig0)), si1 = 1.f/(1.f + expf(-ig1));
                float sf0 = 1.f/(1.f + expf(-fg0)), sf1 = 1.f/(1.f + expf(-fg1));
                float so0 = 1.f/(1.f + expf(-og0)), so1 = 1.f/(1.f + expf(-og1));
                float c0 = sf0*cin.x + si0*tanhf(gg0);
                float c1 = sf1*cin.y + si1*tanhf(gg1);
                *(float2*)&g_c[(size_t)row*HID + u0] = make_float2(c0, c1);
                if (wr_h) {
                    float h0 = so0*tanhf(c0);
                    float h1 = so1*tanhf(c1);
                    float d = deltas[row*SEQ_LEN + t + 1];
                    float hd0 = h0 * expf(-fmaxf(d*ws.x + bd.x, 0.f));
                    float hd1 = h1 * expf(-fmaxf(d*ws.y + bd.y, 0.f));
                    __nv_bfloat162 hp;
                    hp.x = __float2bfloat16(hd0);
                    hp.y = __float2bfloat16(hd1);
                    *(__nv_bfloat162*)&hbf_out[(size_t)row*HW + u0] = hp;
                    part[mi*2+r] += hd0*wr.x + hd1*wr.y;
                }
            }
        }
    }
    if (wr_h) {
        #pragma unroll
        for (int e = 0; e < 4; e++) {
            part[e] += __shfl_xor_sync(0xffffffffu, part[e], 1);
            part[e] += __shfl_xor_sync(0xffffffffu, part[e], 2);
        }
        if (q == 0) {
            int grp = colBlk*2 + wn;
            #pragma unroll
            for (int mi = 0; mi < 2; mi++)
                #pragma unroll
                for (int r = 0; r < 2; r++)
                    g_xhp[grp][row_b + mi*16 + r*8] = part[mi*2+r];
        }
    }
}

// ---------------- deterministic loss reduction ----------------
__global__ void k_loss1() {
    int t = blockIdx.x, tid = threadIdx.x;
    float sn = 0.f, sd = 0.f;
    for (int b = tid; b < BATCH; b += 256) { sn += g_numbuf[t][b]; sd += g_denbuf[t][b]; }
    __shared__ float rn[256], rd[256];
    rn[tid] = sn; rd[tid] = sd;
    __syncthreads();
    for (int o = 128; o > 0; o >>= 1) {
        if (tid < o) { rn[tid] += rn[tid+o]; rd[tid] += rd[tid+o]; }
        __syncthreads();
    }
    if (tid == 0) g_stepw[t] = rn[0] / (rd[0] + 1e-5f);
}
__global__ void k_loss2(float* __restrict__ out) {
    if (threadIdx.x == 0 && blockIdx.x == 0) {
        float s = 0.f;
        for (int t = 0; t < SEQ_LEN; t++) s += g_stepw[t];
        out[0] = s / (float)SEQ_LEN;
    }
}

extern "C" void kernel_launch(void* const* d_in, const int* in_sizes, int n_in,
                              void* d_out, int out_size) {
    const float* values  = (const float*)d_in[0];
    const float* masks   = (const float*)d_in[1];
    const float* deltas  = (const float*)d_in[2];
    const float* W_decay = (const float*)d_in[3];
    const float* b_decay = (const float*)d_in[4];
    const float* W_reg   = (const float*)d_in[5];
    const float* b_reg   = (const float*)d_in[6];
    const float* W_ih    = (const float*)d_in[7];
    const float* W_hh    = (const float*)d_in[8];
    const float* b_ih    = (const float*)d_in[9];
    const float* b_hh    = (const float*)d_in[10];
    float* out = (float*)d_out;
    float* out_imp = out + 1;

    cudaFuncSetAttribute(k_step, cudaFuncAttributeMaxDynamicSharedMemorySize, SMEMSZ);

    k_init<<<(BATCH*HW + 255)/256, 256>>>(W_decay);
    k_vpack<<<(int)(((size_t)SEQ_LEN*BATCH*VW + 255)/256), 256>>>(values, masks);
    k_pack<<<(int)(((size_t)NPCOL*KP2 + 255)/256), 256>>>(W_ih, W_hh, b_ih, b_hh);

    for (int t = 0; t < SEQ_LEN; t++) {
        k_xh<<<BATCH/256, 256>>>(values, masks, b_reg, out_imp, t);
        dim3 grid(13, BATCH/128);          // (13, 64)
        k_step<<<grid, 256, SMEMSZ>>>(deltas, b_decay, W_reg, t);
    }
    k_loss1<<<SEQ_LEN, 256>>>();
    k_loss2<<<1, 32>>>(out);
}